// round 2
// baseline (speedup 1.0000x reference)
#include <cuda_runtime.h>
#include <cuda_bf16.h>
#include <cstdint>

#define DEV_INLINE __device__ __forceinline__

constexpr int NN = 8192;   // nodes
constexpr int DF = 256;    // feature dim

// ---------------- intermediates (static device globals; no runtime alloc) ----
__device__ float g_inv_deg[NN];
__device__ float g_ysT[(size_t)DF * NN];   // [d][j] = tf32( inv_deg[j] * (x@W)[j][d] )

// ============================================================================
// helpers (baseline sm_103 ISA only: cp.async, ldmatrix, mma.sync)
// ============================================================================
DEV_INLINE uint32_t smem_u32(const void* p) {
    uint32_t a;
    asm("{ .reg .u64 t; cvta.to.shared.u64 t, %1; cvt.u32.u64 %0, t; }" : "=r"(a) : "l"(p));
    return a;
}
DEV_INLINE void cp16(uint32_t saddr, const void* g) {
    asm volatile("cp.async.cg.shared.global [%0], [%1], 16;" :: "r"(saddr), "l"(g));
}
DEV_INLINE void cp_commit() { asm volatile("cp.async.commit_group;"); }
template <int N> DEV_INLINE void cp_wait() { asm volatile("cp.async.wait_group %0;" :: "n"(N)); }

DEV_INLINE void ldsm4(uint32_t* d, uint32_t addr) {
    asm volatile("ldmatrix.sync.aligned.m8n8.x4.shared.b16 {%0,%1,%2,%3}, [%4];"
                 : "=r"(d[0]), "=r"(d[1]), "=r"(d[2]), "=r"(d[3]) : "r"(addr));
}
DEV_INLINE uint32_t f2tf32(float x) {
    uint32_t u;
    asm("cvt.rna.tf32.f32 %0, %1;" : "=r"(u) : "f"(x));
    return u;
}
DEV_INLINE void mma_tf32(float* c, const uint32_t* a, const uint32_t* b) {
    asm volatile(
        "mma.sync.aligned.m16n8k8.row.col.f32.tf32.tf32.f32 "
        "{%0,%1,%2,%3}, {%4,%5,%6,%7}, {%8,%9}, {%0,%1,%2,%3};"
        : "+f"(c[0]), "+f"(c[1]), "+f"(c[2]), "+f"(c[3])
        : "r"(a[0]), "r"(a[1]), "r"(a[2]), "r"(a[3]), "r"(b[0]), "r"(b[1]));
}

// ============================================================================
// Kernel 1: inv_deg[i] = 1 / rowsum(A[i,:])     (HBM-bound, 268 MB)
// ============================================================================
__global__ void __launch_bounds__(256) rowsum_kernel(const float* __restrict__ A) {
    int row = blockIdx.x;
    const float4* r4 = reinterpret_cast<const float4*>(A + (size_t)row * NN);
    float s = 0.f;
#pragma unroll
    for (int it = 0; it < (NN / 4) / 256; it++) {
        float4 v = r4[it * 256 + threadIdx.x];
        s += (v.x + v.y) + (v.z + v.w);
    }
    __shared__ float red[256];
    red[threadIdx.x] = s;
    __syncthreads();
#pragma unroll
    for (int o = 128; o > 0; o >>= 1) {
        if (threadIdx.x < o) red[threadIdx.x] += red[threadIdx.x + o];
        __syncthreads();
    }
    if (threadIdx.x == 0) g_inv_deg[row] = 1.0f / red[0];
}

// ============================================================================
// Kernel 2: ysT[d][j] = tf32( inv_deg[j] * (x @ W)[j][d] )   (fp32 FFMA)
// 32 x-rows per CTA, 8x4 register blocking, transposed coalesced store.
// ============================================================================
__global__ void __launch_bounds__(256) xw_kernel(const float* __restrict__ x,
                                                 const float* __restrict__ W) {
    __shared__ float xs[32][DF + 1];
    int r0 = blockIdx.x * 32;
    for (int idx = threadIdx.x; idx < 32 * DF; idx += 256) {
        int r = idx >> 8, c = idx & 255;
        xs[r][c] = x[(size_t)(r0 + r) * DF + c];
    }
    __syncthreads();

    int tx = threadIdx.x & 63;   // 4 output cols: 4*tx .. 4*tx+3
    int ty = threadIdx.x >> 6;   // 8 output rows: 8*ty .. 8*ty+7
    float acc[8][4];
#pragma unroll
    for (int r = 0; r < 8; r++)
#pragma unroll
        for (int c = 0; c < 4; c++) acc[r][c] = 0.f;

    const float4* W4 = reinterpret_cast<const float4*>(W);
#pragma unroll 4
    for (int k = 0; k < DF; k++) {
        float4 w = W4[k * 64 + tx];
        float xv[8];
#pragma unroll
        for (int r = 0; r < 8; r++) xv[r] = xs[ty * 8 + r][k];
#pragma unroll
        for (int r = 0; r < 8; r++) {
            acc[r][0] = fmaf(xv[r], w.x, acc[r][0]);
            acc[r][1] = fmaf(xv[r], w.y, acc[r][1]);
            acc[r][2] = fmaf(xv[r], w.z, acc[r][2]);
            acc[r][3] = fmaf(xv[r], w.w, acc[r][3]);
        }
    }
    __syncthreads();           // done reading xs as x; reuse as y
#pragma unroll
    for (int r = 0; r < 8; r++)
#pragma unroll
        for (int c = 0; c < 4; c++) xs[ty * 8 + r][tx * 4 + c] = acc[r][c];
    __syncthreads();

    int d = threadIdx.x;
#pragma unroll
    for (int r = 0; r < 32; r += 4) {
        float4 o;
        o.x = __uint_as_float(f2tf32(xs[r + 0][d] * g_inv_deg[r0 + r + 0]));
        o.y = __uint_as_float(f2tf32(xs[r + 1][d] * g_inv_deg[r0 + r + 1]));
        o.z = __uint_as_float(f2tf32(xs[r + 2][d] * g_inv_deg[r0 + r + 2]));
        o.w = __uint_as_float(f2tf32(xs[r + 3][d] * g_inv_deg[r0 + r + 3]));
        *reinterpret_cast<float4*>(&g_ysT[(size_t)d * NN + r0 + r]) = o;
    }
}

// ============================================================================
// Kernel 3: out = relu(inv_deg_i * (A @ Y) + bias)
// Legacy mma.sync tf32 GEMM: BM=128, BN=128, BK=32, 4-stage cp.async pipeline.
// Warp grid 2(m) x 4(n); warp tile 64x32; fragments via ldmatrix.x4.
// Grid = (8192/128) x (256/128) = 64 x 2 = 128 CTAs (single wave).
// ============================================================================
constexpr int BM = 128, BN = 128, BK = 32;
constexpr int STAGES = 4;
constexpr int NK = NN / BK;                      // 256
constexpr int SKA = BK + 4;                      // padded row: 36 floats = 144 B
constexpr int TILE_BYTES = BM * SKA * 4;         // 18432 B (A tile; B tile identical)
constexpr int STAGE_BYTES = 2 * TILE_BYTES;      // 36864 B
constexpr int SMEM_GEMM = STAGES * STAGE_BYTES + 2 * BM * 4;   // +invd/bias tiles

__global__ void __launch_bounds__(256, 1) gcn_gemm_kernel(const float* __restrict__ A,
                                                          const float* __restrict__ bias,
                                                          float* __restrict__ out) {
    extern __shared__ char smem[];
    const uint32_t sbase = smem_u32(smem);
    float* invd_s = reinterpret_cast<float*>(smem + STAGES * STAGE_BYTES);
    float* bias_s = invd_s + BM;

    const int tid  = threadIdx.x;
    const int wid  = tid >> 5;
    const int lane = tid & 31;
    const int wm   = wid >> 2;          // 0..1 : 64-row slab
    const int wn   = wid & 3;           // 0..3 : 32-col slab
    const int mbase = blockIdx.x * BM;
    const int nbase = blockIdx.y * BN;

    if (tid < BM) {
        invd_s[tid] = g_inv_deg[mbase + tid];
        bias_s[tid] = bias[nbase + tid];
    }

    // --- per-thread ldmatrix source offsets (q = matrix index within x4)
    const int q = lane >> 3, r = lane & 7;
    // A x4: {rows+0..7,k0..3},{rows+8..15,k0..3},{rows+0..7,k4..7},{rows+8..15,k4..7}
    const uint32_t aoff = (uint32_t)((wm * 64 + (q & 1) * 8 + r) * (SKA * 4) + (q >> 1) * 16);
    // B x4: {nt even,k0..3},{nt even,k4..7},{nt odd,k0..3},{nt odd,k4..7}
    const uint32_t boff = (uint32_t)((wn * 32 + (q >> 1) * 8 + r) * (SKA * 4) + (q & 1) * 16);

    // --- stage loader: A tile 1024 chunks + B tile 1024 chunks, 16B each
    auto load_stage = [&](int st, int kt) {
        const uint32_t sA = sbase + st * STAGE_BYTES;
        const uint32_t sB = sA + TILE_BYTES;
        const int k0 = kt * BK;
#pragma unroll
        for (int i = 0; i < 8; i++) {
            int c = i * 256 + tid;            // 0..2047
            int row = (c >> 3) & 127;
            int cq  = c & 7;
            if (c < 1024) {
                cp16(sA + row * (SKA * 4) + cq * 16,
                     A + (size_t)(mbase + row) * NN + k0 + cq * 4);
            } else {
                cp16(sB + row * (SKA * 4) + cq * 16,
                     g_ysT + (size_t)(nbase + row) * NN + k0 + cq * 4);
            }
        }
    };

    float acc[4][4][4];
#pragma unroll
    for (int mt = 0; mt < 4; mt++)
#pragma unroll
        for (int nt = 0; nt < 4; nt++)
#pragma unroll
            for (int i = 0; i < 4; i++) acc[mt][nt][i] = 0.f;

    // --- prologue: stages 0..2
    load_stage(0, 0); cp_commit();
    load_stage(1, 1); cp_commit();
    load_stage(2, 2); cp_commit();

    for (int kt = 0; kt < NK; kt++) {
        cp_wait<STAGES - 2>();
        __syncthreads();

        // prefetch kt+3 into the stage freed by iteration kt-1
        if (kt + STAGES - 1 < NK) {
            load_stage((kt + STAGES - 1) & (STAGES - 1), kt + STAGES - 1);
            cp_commit();
        }

        const uint32_t sA = sbase + (kt & (STAGES - 1)) * STAGE_BYTES;
        const uint32_t sB = sA + TILE_BYTES;
#pragma unroll
        for (int ks = 0; ks < 4; ks++) {
            uint32_t afr[4][4];
#pragma unroll
            for (int mt = 0; mt < 4; mt++) {
                ldsm4(afr[mt], sA + aoff + mt * (16 * SKA * 4) + ks * 32);
#pragma unroll
                for (int i = 0; i < 4; i++)
                    afr[mt][i] = f2tf32(__uint_as_float(afr[mt][i]));
            }
            uint32_t bfr[2][4];
#pragma unroll
            for (int np = 0; np < 2; np++)
                ldsm4(bfr[np], sB + boff + np * (16 * SKA * 4) + ks * 32);
            // (B already tf32-rounded at producer — no cvt)
#pragma unroll
            for (int mt = 0; mt < 4; mt++)
#pragma unroll
                for (int nt = 0; nt < 4; nt++)
                    mma_tf32(acc[mt][nt], afr[mt], &bfr[nt >> 1][(nt & 1) * 2]);
        }
    }

    // --- epilogue: scale by inv_deg(row), add bias, relu, store float2
    const int g2 = lane >> 2, t2 = lane & 3;
#pragma unroll
    for (int mt = 0; mt < 4; mt++) {
        const int rl = wm * 64 + mt * 16 + g2;        // local row
        const float s0 = invd_s[rl], s1 = invd_s[rl + 8];
        float* o0 = out + (size_t)(mbase + rl) * DF + nbase + wn * 32;
        float* o1 = o0 + (size_t)8 * DF;
#pragma unroll
        for (int nt = 0; nt < 4; nt++) {
            const int c = nt * 8 + t2 * 2;
            const float b0 = bias_s[wn * 32 + c], b1 = bias_s[wn * 32 + c + 1];
            float2 v0, v1;
            v0.x = fmaxf(fmaf(acc[mt][nt][0], s0, b0), 0.f);
            v0.y = fmaxf(fmaf(acc[mt][nt][1], s0, b1), 0.f);
            v1.x = fmaxf(fmaf(acc[mt][nt][2], s1, b0), 0.f);
            v1.y = fmaxf(fmaf(acc[mt][nt][3], s1, b1), 0.f);
            *reinterpret_cast<float2*>(o0 + c) = v0;
            *reinterpret_cast<float2*>(o1 + c) = v1;
        }
    }
}

// ============================================================================
// Launch
// ============================================================================
extern "C" void kernel_launch(void* const* d_in, const int* in_sizes, int n_in,
                              void* d_out, int out_size) {
    const float* x    = (const float*)d_in[0];   // [8192,256]
    const float* adj  = (const float*)d_in[1];   // [8192,8192]
    const float* W    = (const float*)d_in[2];   // [256,256]
    const float* bias = (const float*)d_in[3];   // [256]
    float* out = (float*)d_out;                  // [8192,256]

    cudaFuncSetAttribute(gcn_gemm_kernel, cudaFuncAttributeMaxDynamicSharedMemorySize,
                         SMEM_GEMM);

    rowsum_kernel<<<NN, 256>>>(adj);
    xw_kernel<<<NN / 32, 256>>>(x, W);
    dim3 grid(NN / BM, DF / BN);   // 64 x 2
    gcn_gemm_kernel<<<grid, 256, SMEM_GEMM>>>(adj, bias, out);
}

// round 3
// speedup vs baseline: 1.5067x; 1.5067x over previous
#include <cuda_runtime.h>
#include <cuda_fp16.h>
#include <cstdint>

#define DEV_INLINE __device__ __forceinline__

constexpr int NN = 8192;   // nodes
constexpr int DF = 256;    // feature dim
constexpr float YSCALE = 4096.f;   // exact pow2: keeps Y out of fp16 subnormals

// ---------------- intermediates (static device globals; no runtime alloc) ----
__device__ float  g_inv_deg[NN];
__device__ __half g_Ah[(size_t)NN * NN];     // fp16 copy of adjacency (rna)
__device__ __half g_ysTh[(size_t)DF * NN];   // [d][j] = fp16( YSCALE*inv_j*(xW)[j][d] )

// ============================================================================
// helpers (baseline sm_103 ISA only: cp.async, ldmatrix, mma.sync)
// ============================================================================
DEV_INLINE uint32_t smem_u32(const void* p) {
    uint32_t a;
    asm("{ .reg .u64 t; cvta.to.shared.u64 t, %1; cvt.u32.u64 %0, t; }" : "=r"(a) : "l"(p));
    return a;
}
DEV_INLINE void cp16(uint32_t saddr, const void* g) {
    asm volatile("cp.async.cg.shared.global [%0], [%1], 16;" :: "r"(saddr), "l"(g));
}
DEV_INLINE void cp_commit() { asm volatile("cp.async.commit_group;"); }
template <int N> DEV_INLINE void cp_wait() { asm volatile("cp.async.wait_group %0;" :: "n"(N)); }

DEV_INLINE void ldsm4(uint32_t* d, uint32_t addr) {
    asm volatile("ldmatrix.sync.aligned.m8n8.x4.shared.b16 {%0,%1,%2,%3}, [%4];"
                 : "=r"(d[0]), "=r"(d[1]), "=r"(d[2]), "=r"(d[3]) : "r"(addr));
}
DEV_INLINE void mma_f16(float* c, const uint32_t* a, const uint32_t* b) {
    asm volatile(
        "mma.sync.aligned.m16n8k16.row.col.f32.f16.f16.f32 "
        "{%0,%1,%2,%3}, {%4,%5,%6,%7}, {%8,%9}, {%0,%1,%2,%3};"
        : "+f"(c[0]), "+f"(c[1]), "+f"(c[2]), "+f"(c[3])
        : "r"(a[0]), "r"(a[1]), "r"(a[2]), "r"(a[3]), "r"(b[0]), "r"(b[1]));
}

// ============================================================================
// Kernel 1: inv_deg[i] = 1/rowsum(A[i,:]); also emits fp16 copy of A.
// 268 MB read + 134 MB write, HBM-bound (~60 us).
// ============================================================================
__global__ void __launch_bounds__(256) rowsum_kernel(const float* __restrict__ A) {
    int row = blockIdx.x;
    const float4* r4 = reinterpret_cast<const float4*>(A + (size_t)row * NN);
    __half* ah = g_Ah + (size_t)row * NN;
    float s = 0.f;
#pragma unroll
    for (int it = 0; it < (NN / 4) / 256; it++) {
        int idx = it * 256 + threadIdx.x;
        float4 v = r4[idx];
        s += (v.x + v.y) + (v.z + v.w);
        union { __half2 h[2]; uint2 u; } p;
        p.h[0] = __floats2half2_rn(v.x, v.y);
        p.h[1] = __floats2half2_rn(v.z, v.w);
        *reinterpret_cast<uint2*>(ah + (size_t)idx * 4) = p.u;
    }
    __shared__ float red[256];
    red[threadIdx.x] = s;
    __syncthreads();
#pragma unroll
    for (int o = 128; o > 0; o >>= 1) {
        if (threadIdx.x < o) red[threadIdx.x] += red[threadIdx.x + o];
        __syncthreads();
    }
    if (threadIdx.x == 0) g_inv_deg[row] = 1.0f / red[0];
}

// ============================================================================
// Kernel 2: ysTh[d][j] = fp16( YSCALE * inv_deg[j] * (x @ W)[j][d] )
// 32 x-rows per CTA, 8x4 register blocking, transposed coalesced fp16 store.
// ============================================================================
__global__ void __launch_bounds__(256) xw_kernel(const float* __restrict__ x,
                                                 const float* __restrict__ W) {
    __shared__ float xs[32][DF + 1];
    int r0 = blockIdx.x * 32;
    for (int idx = threadIdx.x; idx < 32 * DF; idx += 256) {
        int r = idx >> 8, c = idx & 255;
        xs[r][c] = x[(size_t)(r0 + r) * DF + c];
    }
    __syncthreads();

    int tx = threadIdx.x & 63;   // 4 output cols: 4*tx .. 4*tx+3
    int ty = threadIdx.x >> 6;   // 8 output rows: 8*ty .. 8*ty+7
    float acc[8][4];
#pragma unroll
    for (int r = 0; r < 8; r++)
#pragma unroll
        for (int c = 0; c < 4; c++) acc[r][c] = 0.f;

    const float4* W4 = reinterpret_cast<const float4*>(W);
#pragma unroll 4
    for (int k = 0; k < DF; k++) {
        float4 w = W4[k * 64 + tx];
        float xv[8];
#pragma unroll
        for (int r = 0; r < 8; r++) xv[r] = xs[ty * 8 + r][k];
#pragma unroll
        for (int r = 0; r < 8; r++) {
            acc[r][0] = fmaf(xv[r], w.x, acc[r][0]);
            acc[r][1] = fmaf(xv[r], w.y, acc[r][1]);
            acc[r][2] = fmaf(xv[r], w.z, acc[r][2]);
            acc[r][3] = fmaf(xv[r], w.w, acc[r][3]);
        }
    }
    __syncthreads();           // done reading xs as x; reuse as y
#pragma unroll
    for (int r = 0; r < 8; r++)
#pragma unroll
        for (int c = 0; c < 4; c++) xs[ty * 8 + r][tx * 4 + c] = acc[r][c];
    __syncthreads();

    int d = threadIdx.x;
#pragma unroll
    for (int r = 0; r < 32; r += 4) {
        float s0 = g_inv_deg[r0 + r + 0] * YSCALE;
        float s1 = g_inv_deg[r0 + r + 1] * YSCALE;
        float s2 = g_inv_deg[r0 + r + 2] * YSCALE;
        float s3 = g_inv_deg[r0 + r + 3] * YSCALE;
        union { __half2 h[2]; uint2 u; } p;
        p.h[0] = __floats2half2_rn(xs[r + 0][d] * s0, xs[r + 1][d] * s1);
        p.h[1] = __floats2half2_rn(xs[r + 2][d] * s2, xs[r + 3][d] * s3);
        *reinterpret_cast<uint2*>(&g_ysTh[(size_t)d * NN + r0 + r]) = p.u;
    }
}

// ============================================================================
// Kernel 3: out = relu( (inv_deg_i/YSCALE) * (Ah @ Yh) + bias )
// fp16 mma.sync m16n8k16 GEMM: BM=128, BN=128, BK=64, 4-stage cp.async.
// Warp grid 2(m) x 4(n); warp tile 64x32. Grid 64x2 = 128 CTAs, single wave.
// ============================================================================
constexpr int BM = 128, BN = 128, BK = 64;
constexpr int STAGES = 4;
constexpr int NK = NN / BK;                   // 128
constexpr int SKH = BK + 8;                   // padded row: 72 halves = 144 B
constexpr int ROWB = SKH * 2;                 // 144
constexpr int TILE_BYTES = BM * ROWB;         // 18432 (A tile; B tile identical)
constexpr int STAGE_BYTES = 2 * TILE_BYTES;   // 36864
constexpr int SMEM_GEMM = STAGES * STAGE_BYTES + 2 * BM * 4;   // 148480

__global__ void __launch_bounds__(256, 1) gcn_gemm_kernel(const float* __restrict__ bias,
                                                          float* __restrict__ out) {
    extern __shared__ char smem[];
    const uint32_t sbase = smem_u32(smem);
    float* invd_s = reinterpret_cast<float*>(smem + STAGES * STAGE_BYTES);
    float* bias_s = invd_s + BM;

    const int tid  = threadIdx.x;
    const int wid  = tid >> 5;
    const int lane = tid & 31;
    const int wm   = wid >> 2;          // 0..1 : 64-row slab
    const int wn   = wid & 3;           // 0..3 : 32-col slab
    const int mbase = blockIdx.x * BM;
    const int nbase = blockIdx.y * BN;

    if (tid < BM) {
        invd_s[tid] = g_inv_deg[mbase + tid] * (1.0f / YSCALE);
        bias_s[tid] = bias[nbase + tid];
    }

    // --- per-thread ldmatrix source offsets (q = matrix index within x4)
    const int q = lane >> 3, r = lane & 7;
    // A x4: {rows+0..7,k0..7},{rows+8..15,k0..7},{rows+0..7,k8..15},{rows+8..15,k8..15}
    const uint32_t aoff = (uint32_t)((wm * 64 + (q & 1) * 8 + r) * ROWB + (q >> 1) * 16);
    // B x4: {n+0..7,k0..7},{n+0..7,k8..15},{n+8..15,k0..7},{n+8..15,k8..15}
    const uint32_t boff = (uint32_t)((wn * 32 + (q >> 1) * 8 + r) * ROWB + (q & 1) * 16);

    // --- stage loader: A tile 1024 chunks + B tile 1024 chunks, 16B each
    auto load_stage = [&](int st, int kt) {
        const uint32_t sA = sbase + st * STAGE_BYTES;
        const uint32_t sB = sA + TILE_BYTES;
        const int k0 = kt * BK;
#pragma unroll
        for (int i = 0; i < 8; i++) {
            int c = i * 256 + tid;            // 0..2047
            int row = (c >> 3) & 127;
            int cq  = c & 7;
            if (c < 1024) {
                cp16(sA + row * ROWB + cq * 16,
                     g_Ah + (size_t)(mbase + row) * NN + k0 + cq * 8);
            } else {
                cp16(sB + row * ROWB + cq * 16,
                     g_ysTh + (size_t)(nbase + row) * NN + k0 + cq * 8);
            }
        }
    };

    float acc[4][4][4];
#pragma unroll
    for (int mt = 0; mt < 4; mt++)
#pragma unroll
        for (int nt = 0; nt < 4; nt++)
#pragma unroll
            for (int i = 0; i < 4; i++) acc[mt][nt][i] = 0.f;

    // --- prologue: stages 0..2
    load_stage(0, 0); cp_commit();
    load_stage(1, 1); cp_commit();
    load_stage(2, 2); cp_commit();

    for (int kt = 0; kt < NK; kt++) {
        cp_wait<STAGES - 2>();
        __syncthreads();

        // prefetch kt+3 into the stage freed by iteration kt-1
        if (kt + STAGES - 1 < NK) {
            load_stage((kt + STAGES - 1) & (STAGES - 1), kt + STAGES - 1);
        }
        cp_commit();

        const uint32_t sA = sbase + (kt & (STAGES - 1)) * STAGE_BYTES;
        const uint32_t sB = sA + TILE_BYTES;
#pragma unroll
        for (int ks = 0; ks < 4; ks++) {       // 4 x k16 steps
            uint32_t afr[4][4];
#pragma unroll
            for (int mt = 0; mt < 4; mt++)
                ldsm4(afr[mt], sA + aoff + mt * (16 * ROWB) + ks * 32);
            uint32_t bfr[2][4];
#pragma unroll
            for (int np = 0; np < 2; np++)
                ldsm4(bfr[np], sB + boff + np * (16 * ROWB) + ks * 32);
#pragma unroll
            for (int mt = 0; mt < 4; mt++)
#pragma unroll
                for (int nt = 0; nt < 4; nt++)
                    mma_f16(acc[mt][nt], afr[mt], &bfr[nt >> 1][(nt & 1) * 2]);
        }
    }

    // --- epilogue: scale by inv_deg(row)/YSCALE, add bias, relu, store float2
    const int g2 = lane >> 2, t2 = lane & 3;
#pragma unroll
    for (int mt = 0; mt < 4; mt++) {
        const int rl = wm * 64 + mt * 16 + g2;        // local row
        const float s0 = invd_s[rl], s1 = invd_s[rl + 8];
        float* o0 = out + (size_t)(mbase + rl) * DF + nbase + wn * 32;
        float* o1 = o0 + (size_t)8 * DF;
#pragma unroll
        for (int nt = 0; nt < 4; nt++) {
            const int c = nt * 8 + t2 * 2;
            const float b0 = bias_s[wn * 32 + c], b1 = bias_s[wn * 32 + c + 1];
            float2 v0, v1;
            v0.x = fmaxf(fmaf(acc[mt][nt][0], s0, b0), 0.f);
            v0.y = fmaxf(fmaf(acc[mt][nt][1], s0, b1), 0.f);
            v1.x = fmaxf(fmaf(acc[mt][nt][2], s1, b0), 0.f);
            v1.y = fmaxf(fmaf(acc[mt][nt][3], s1, b1), 0.f);
            *reinterpret_cast<float2*>(o0 + c) = v0;
            *reinterpret_cast<float2*>(o1 + c) = v1;
        }
    }
}

// ============================================================================
// Launch
// ============================================================================
extern "C" void kernel_launch(void* const* d_in, const int* in_sizes, int n_in,
                              void* d_out, int out_size) {
    const float* x    = (const float*)d_in[0];   // [8192,256]
    const float* adj  = (const float*)d_in[1];   // [8192,8192]
    const float* W    = (const float*)d_in[2];   // [256,256]
    const float* bias = (const float*)d_in[3];   // [256]
    float* out = (float*)d_out;                  // [8192,256]

    cudaFuncSetAttribute(gcn_gemm_kernel, cudaFuncAttributeMaxDynamicSharedMemorySize,
                         SMEM_GEMM);

    rowsum_kernel<<<NN, 256>>>(adj);
    xw_kernel<<<NN / 32, 256>>>(x, W);
    dim3 grid(NN / BM, DF / BN);   // 64 x 2
    gcn_gemm_kernel<<<grid, 256, SMEM_GEMM>>>(bias, out);
}

// round 4
// speedup vs baseline: 1.5248x; 1.0120x over previous
#include <cuda_runtime.h>
#include <cuda_fp16.h>
#include <cstdint>

#define DEV_INLINE __device__ __forceinline__

constexpr int NN = 8192;   // nodes
constexpr int DF = 256;    // feature dim
constexpr float YSCALE = 4096.f;   // exact pow2: keeps Y out of fp16 subnormals

// ---------------- intermediates (static device globals; no runtime alloc) ----
__device__ float  g_inv_deg[NN];
__device__ __half g_Ah[(size_t)NN * NN];     // fp16 copy of adjacency (rn)
__device__ __half g_ysTh[(size_t)DF * NN];   // [d][j] = fp16( YSCALE*inv_j*(xW)[j][d] )

// ============================================================================
// helpers (baseline sm_103 ISA only: cp.async, ldmatrix, mma.sync)
// ============================================================================
DEV_INLINE uint32_t smem_u32(const void* p) {
    uint32_t a;
    asm("{ .reg .u64 t; cvta.to.shared.u64 t, %1; cvt.u32.u64 %0, t; }" : "=r"(a) : "l"(p));
    return a;
}
DEV_INLINE void cp16(uint32_t saddr, const void* g) {
    asm volatile("cp.async.cg.shared.global [%0], [%1], 16;" :: "r"(saddr), "l"(g));
}
DEV_INLINE void cp_commit() { asm volatile("cp.async.commit_group;"); }
template <int N> DEV_INLINE void cp_wait() { asm volatile("cp.async.wait_group %0;" :: "n"(N)); }

DEV_INLINE void ldsm4(uint32_t* d, uint32_t addr) {
    asm volatile("ldmatrix.sync.aligned.m8n8.x4.shared.b16 {%0,%1,%2,%3}, [%4];"
                 : "=r"(d[0]), "=r"(d[1]), "=r"(d[2]), "=r"(d[3]) : "r"(addr));
}
DEV_INLINE void mma_f16(float* c, const uint32_t* a, const uint32_t* b) {
    asm volatile(
        "mma.sync.aligned.m16n8k16.row.col.f32.f16.f16.f32 "
        "{%0,%1,%2,%3}, {%4,%5,%6,%7}, {%8,%9}, {%0,%1,%2,%3};"
        : "+f"(c[0]), "+f"(c[1]), "+f"(c[2]), "+f"(c[3])
        : "r"(a[0]), "r"(a[1]), "r"(a[2]), "r"(a[3]), "r"(b[0]), "r"(b[1]));
}

// ============================================================================
// Kernel 1: inv_deg[i] = 1/rowsum(A[i,:]); also emits fp16 copy of A.
// 268 MB read + 134 MB write, HBM-bound (~54 us measured).
// ============================================================================
__global__ void __launch_bounds__(256) rowsum_kernel(const float* __restrict__ A) {
    int row = blockIdx.x;
    const float4* r4 = reinterpret_cast<const float4*>(A + (size_t)row * NN);
    __half* ah = g_Ah + (size_t)row * NN;
    float s = 0.f;
#pragma unroll
    for (int it = 0; it < (NN / 4) / 256; it++) {
        int idx = it * 256 + threadIdx.x;
        float4 v = r4[idx];
        s += (v.x + v.y) + (v.z + v.w);
        union { __half2 h[2]; uint2 u; } p;
        p.h[0] = __floats2half2_rn(v.x, v.y);
        p.h[1] = __floats2half2_rn(v.z, v.w);
        *reinterpret_cast<uint2*>(ah + (size_t)idx * 4) = p.u;
    }
    __shared__ float red[256];
    red[threadIdx.x] = s;
    __syncthreads();
#pragma unroll
    for (int o = 128; o > 0; o >>= 1) {
        if (threadIdx.x < o) red[threadIdx.x] += red[threadIdx.x + o];
        __syncthreads();
    }
    if (threadIdx.x == 0) g_inv_deg[row] = 1.0f / red[0];
}

// ============================================================================
// Kernel 2: ysTh[d][j] = fp16( YSCALE * inv_deg[j] * (x @ W)[j][d] )
// ============================================================================
__global__ void __launch_bounds__(256) xw_kernel(const float* __restrict__ x,
                                                 const float* __restrict__ W) {
    __shared__ float xs[32][DF + 1];
    int r0 = blockIdx.x * 32;
    for (int idx = threadIdx.x; idx < 32 * DF; idx += 256) {
        int r = idx >> 8, c = idx & 255;
        xs[r][c] = x[(size_t)(r0 + r) * DF + c];
    }
    __syncthreads();

    int tx = threadIdx.x & 63;
    int ty = threadIdx.x >> 6;
    float acc[8][4];
#pragma unroll
    for (int r = 0; r < 8; r++)
#pragma unroll
        for (int c = 0; c < 4; c++) acc[r][c] = 0.f;

    const float4* W4 = reinterpret_cast<const float4*>(W);
#pragma unroll 4
    for (int k = 0; k < DF; k++) {
        float4 w = W4[k * 64 + tx];
        float xv[8];
#pragma unroll
        for (int r = 0; r < 8; r++) xv[r] = xs[ty * 8 + r][k];
#pragma unroll
        for (int r = 0; r < 8; r++) {
            acc[r][0] = fmaf(xv[r], w.x, acc[r][0]);
            acc[r][1] = fmaf(xv[r], w.y, acc[r][1]);
            acc[r][2] = fmaf(xv[r], w.z, acc[r][2]);
            acc[r][3] = fmaf(xv[r], w.w, acc[r][3]);
        }
    }
    __syncthreads();
#pragma unroll
    for (int r = 0; r < 8; r++)
#pragma unroll
        for (int c = 0; c < 4; c++) xs[ty * 8 + r][tx * 4 + c] = acc[r][c];
    __syncthreads();

    int d = threadIdx.x;
#pragma unroll
    for (int r = 0; r < 32; r += 4) {
        float s0 = g_inv_deg[r0 + r + 0] * YSCALE;
        float s1 = g_inv_deg[r0 + r + 1] * YSCALE;
        float s2 = g_inv_deg[r0 + r + 2] * YSCALE;
        float s3 = g_inv_deg[r0 + r + 3] * YSCALE;
        union { __half2 h[2]; uint2 u; } p;
        p.h[0] = __floats2half2_rn(xs[r + 0][d] * s0, xs[r + 1][d] * s1);
        p.h[1] = __floats2half2_rn(xs[r + 2][d] * s2, xs[r + 3][d] * s3);
        *reinterpret_cast<uint2*>(&g_ysTh[(size_t)d * NN + r0 + r]) = p.u;
    }
}

// ============================================================================
// Kernel 3: out = relu( (inv_deg_i/YSCALE) * (Ah @ Yh) + bias )
// fp16 mma.sync m16n8k16: BM=128, BN=128, BK=128, 3-stage cp.async, 512 thr.
// Warp grid 4(m) x 4(n); warp tile 32x32. Grid 64x2 = 128 CTAs, single wave.
// ============================================================================
constexpr int BM = 128, BN = 128, BK = 128;
constexpr int STAGES = 3;
constexpr int NK = NN / BK;                   // 64
constexpr int SKH = BK + 8;                   // padded row: 136 halves = 272 B
constexpr int ROWB = SKH * 2;                 // 272
constexpr int TILE_BYTES = BM * ROWB;         // 34816 (A tile; B tile identical)
constexpr int STAGE_BYTES = 2 * TILE_BYTES;   // 69632
constexpr int SMEM_GEMM = STAGES * STAGE_BYTES + 2 * BM * 4;   // 209920

__global__ void __launch_bounds__(512, 1) gcn_gemm_kernel(const float* __restrict__ bias,
                                                          float* __restrict__ out) {
    extern __shared__ char smem[];
    const uint32_t sbase = smem_u32(smem);
    float* invd_s = reinterpret_cast<float*>(smem + STAGES * STAGE_BYTES);
    float* bias_s = invd_s + BM;

    const int tid  = threadIdx.x;
    const int wid  = tid >> 5;
    const int lane = tid & 31;
    const int wm   = wid >> 2;          // 0..3 : 32-row slab
    const int wn   = wid & 3;           // 0..3 : 32-col slab
    const int mbase = blockIdx.x * BM;
    const int nbase = blockIdx.y * BN;

    if (tid < BM) {
        invd_s[tid] = g_inv_deg[mbase + tid] * (1.0f / YSCALE);
        bias_s[tid] = bias[nbase + tid];
    }

    // --- per-thread ldmatrix source offsets (q = matrix index within x4)
    const int q = lane >> 3, r = lane & 7;
    // A x4: {rows+0..7,k0..7},{rows+8..15,k0..7},{rows+0..7,k8..15},{rows+8..15,k8..15}
    const uint32_t aoff = (uint32_t)((wm * 32 + (q & 1) * 8 + r) * ROWB + (q >> 1) * 16);
    // B x4: {n+0..7,k0..7},{n+0..7,k8..15},{n+8..15,k0..7},{n+8..15,k8..15}
    const uint32_t boff = (uint32_t)((wn * 32 + (q >> 1) * 8 + r) * ROWB + (q & 1) * 16);

    // --- stage loader: A tile 2048 chunks + B tile 2048 chunks, 16B each
    auto load_stage = [&](int st, int kt) {
        const uint32_t sA = sbase + st * STAGE_BYTES;
        const int k0 = kt * BK;
#pragma unroll
        for (int i = 0; i < 8; i++) {
            int c = i * 512 + tid;            // 0..4095
            int row = c >> 4;                 // 0..255 (A: 0-127, B: 128-255)
            int cq  = c & 15;
            if (row < 128) {
                cp16(sA + row * ROWB + cq * 16,
                     g_Ah + (size_t)(mbase + row) * NN + k0 + cq * 8);
            } else {
                cp16(sA + TILE_BYTES + (row - 128) * ROWB + cq * 16,
                     g_ysTh + (size_t)(nbase + row - 128) * NN + k0 + cq * 8);
            }
        }
    };

    float acc[2][4][4];
#pragma unroll
    for (int mt = 0; mt < 2; mt++)
#pragma unroll
        for (int nt = 0; nt < 4; nt++)
#pragma unroll
            for (int i = 0; i < 4; i++) acc[mt][nt][i] = 0.f;

    // --- prologue: stages 0..1
    load_stage(0, 0); cp_commit();
    load_stage(1, 1); cp_commit();

    int st = 0;
    for (int kt = 0; kt < NK; kt++) {
        cp_wait<STAGES - 2>();
        __syncthreads();

        // prefetch kt+2 into the stage consumed at iteration kt-1
        int pst = st + 2 >= STAGES ? st + 2 - STAGES : st + 2;
        if (kt + STAGES - 1 < NK) {
            load_stage(pst, kt + STAGES - 1);
        }
        cp_commit();

        const uint32_t sA = sbase + st * STAGE_BYTES;
        const uint32_t sB = sA + TILE_BYTES;
#pragma unroll
        for (int ks = 0; ks < 8; ks++) {       // 8 x k16 steps
            uint32_t afr[2][4];
#pragma unroll
            for (int mt = 0; mt < 2; mt++)
                ldsm4(afr[mt], sA + aoff + mt * (16 * ROWB) + ks * 32);
            uint32_t bfr[2][4];
#pragma unroll
            for (int np = 0; np < 2; np++)
                ldsm4(bfr[np], sB + boff + np * (16 * ROWB) + ks * 32);
#pragma unroll
            for (int mt = 0; mt < 2; mt++)
#pragma unroll
                for (int nt = 0; nt < 4; nt++)
                    mma_f16(acc[mt][nt], afr[mt], &bfr[nt >> 1][(nt & 1) * 2]);
        }
        st = st + 1 >= STAGES ? 0 : st + 1;
    }

    // --- epilogue: scale by inv_deg(row)/YSCALE, add bias, relu, store float2
    const int g2 = lane >> 2, t2 = lane & 3;
#pragma unroll
    for (int mt = 0; mt < 2; mt++) {
        const int rl = wm * 32 + mt * 16 + g2;        // local row
        const float s0 = invd_s[rl], s1 = invd_s[rl + 8];
        float* o0 = out + (size_t)(mbase + rl) * DF + nbase + wn * 32;
        float* o1 = o0 + (size_t)8 * DF;
#pragma unroll
        for (int nt = 0; nt < 4; nt++) {
            const int c = nt * 8 + t2 * 2;
            const float b0 = bias_s[wn * 32 + c], b1 = bias_s[wn * 32 + c + 1];
            float2 v0, v1;
            v0.x = fmaxf(fmaf(acc[mt][nt][0], s0, b0), 0.f);
            v0.y = fmaxf(fmaf(acc[mt][nt][1], s0, b1), 0.f);
            v1.x = fmaxf(fmaf(acc[mt][nt][2], s1, b0), 0.f);
            v1.y = fmaxf(fmaf(acc[mt][nt][3], s1, b1), 0.f);
            *reinterpret_cast<float2*>(o0 + c) = v0;
            *reinterpret_cast<float2*>(o1 + c) = v1;
        }
    }
}

// ============================================================================
// Launch
// ============================================================================
extern "C" void kernel_launch(void* const* d_in, const int* in_sizes, int n_in,
                              void* d_out, int out_size) {
    const float* x    = (const float*)d_in[0];   // [8192,256]
    const float* adj  = (const float*)d_in[1];   // [8192,8192]
    const float* W    = (const float*)d_in[2];   // [256,256]
    const float* bias = (const float*)d_in[3];   // [256]
    float* out = (float*)d_out;                  // [8192,256]

    cudaFuncSetAttribute(gcn_gemm_kernel, cudaFuncAttributeMaxDynamicSharedMemorySize,
                         SMEM_GEMM);

    rowsum_kernel<<<NN, 256>>>(adj);
    xw_kernel<<<NN / 32, 256>>>(x, W);
    dim3 grid(NN / BM, DF / BN);   // 64 x 2
    gcn_gemm_kernel<<<grid, 512, SMEM_GEMM>>>(bias, out);
}